// round 7
// baseline (speedup 1.0000x reference)
#include <cuda_runtime.h>
#include <cuda_fp16.h>
#include <cstdint>
#include <cstddef>

// Problem dims
#define NQ 8192
#define MC 20000
#define MP 20096            // centers padded: 157*128
#define DD 1024
#define YY 256
#define PADW 20             // smem row stride in 32-bit words (conflict-free at 4B and 16B gran)

// Scratch (device globals; zero-initialized at load)
__device__ __half g_K[(size_t)NQ * MP];    // fp16 kernel matrix
__device__ __half g_Wt[(size_t)YY * MP];   // W transposed, k-contiguous; tail [MC,MP) stays 0
__device__ __half g_Xh[(size_t)NQ * DD];   // fp16 batch
__device__ __half g_Zh[(size_t)MP * DD];   // fp16 centers; tail rows stay 0
__device__ float  g_xsq[NQ];
__device__ float  g_zsq[MP];               // tail stays 0

// ---------------------------------------------------------------------------
// Helpers
// ---------------------------------------------------------------------------
__device__ __forceinline__ void mma_f16(float* c, const uint32_t* a, const uint32_t* b) {
    asm volatile(
        "mma.sync.aligned.m16n8k16.row.col.f32.f16.f16.f32 "
        "{%0,%1,%2,%3},{%4,%5,%6,%7},{%8,%9},{%0,%1,%2,%3};"
        : "+f"(c[0]), "+f"(c[1]), "+f"(c[2]), "+f"(c[3])
        : "r"(a[0]), "r"(a[1]), "r"(a[2]), "r"(a[3]), "r"(b[0]), "r"(b[1]));
}

__device__ __forceinline__ void ldsm_x4(uint32_t* r, uint32_t addr) {
    asm volatile("ldmatrix.sync.aligned.m8n8.x4.shared.b16 {%0,%1,%2,%3}, [%4];"
                 : "=r"(r[0]), "=r"(r[1]), "=r"(r[2]), "=r"(r[3]) : "r"(addr));
}

__device__ __forceinline__ uint32_t smem_u32(const void* p) {
    uint32_t a;
    asm("{ .reg .u64 t; cvta.to.shared.u64 t, %1; cvt.u32.u64 %0, t; }" : "=r"(a) : "l"(p));
    return a;
}

__device__ __forceinline__ uint32_t h2u(__half2 h) {
    return *reinterpret_cast<uint32_t*>(&h);
}

__device__ __forceinline__ float resolve_bw(const void* p) {
    int iv = *(const int*)p;
    if (iv > 0 && iv < 1000000) return (float)iv;
    return *(const float*)p;
}

// ---------------------------------------------------------------------------
// Kernel 0: convert fp32 rows -> fp16 AND compute row squared norms.
// One warp per row (NQ + MC rows).
// ---------------------------------------------------------------------------
__global__ void convert_kernel(const float* __restrict__ x, const float* __restrict__ z) {
    int gwarp = (blockIdx.x * blockDim.x + threadIdx.x) >> 5;
    int lane = threadIdx.x & 31;
    const float* src;
    __half* dh;
    float* dsq;
    if (gwarp < NQ) {
        src = x + (size_t)gwarp * DD; dh = g_Xh + (size_t)gwarp * DD; dsq = g_xsq + gwarp;
    } else if (gwarp < NQ + MC) {
        int r = gwarp - NQ;
        src = z + (size_t)r * DD;     dh = g_Zh + (size_t)r * DD;     dsq = g_zsq + r;
    } else return;

    const float4* p = (const float4*)src;
    uint2* o = (uint2*)dh;
    float s = 0.f;
#pragma unroll
    for (int i = 0; i < DD / 128; i++) {
        float4 v = p[lane + i * 32];
        s += v.x * v.x + v.y * v.y + v.z * v.z + v.w * v.w;
        o[lane + i * 32] = make_uint2(h2u(__floats2half2_rn(v.x, v.y)),
                                      h2u(__floats2half2_rn(v.z, v.w)));
    }
#pragma unroll
    for (int off = 16; off; off >>= 1) s += __shfl_xor_sync(0xffffffffu, s, off);
    if (lane == 0) *dsq = s;
}

// ---------------------------------------------------------------------------
// Kernel 0b: transpose W [MC, YY] fp32 -> g_Wt [YY, MP] fp16
// ---------------------------------------------------------------------------
__global__ void wtrans_kernel(const float* __restrict__ W) {
    __shared__ float t[32][33];
    const int k0 = blockIdx.x * 32;
    const int n0 = blockIdx.y * 32;
    const int tx = threadIdx.x, ty = threadIdx.y;
    t[ty][tx] = W[(size_t)(k0 + ty) * YY + (n0 + tx)];
    __syncthreads();
    g_Wt[(size_t)(n0 + ty) * MP + (k0 + tx)] = __float2half_rn(t[tx][ty]);
}

// ---------------------------------------------------------------------------
// Kernel 1: K[i,j] = exp(-sqrt(max(xsq+zsq-2*X.Z,0))/bw), fp16 out.
// NT GEMM fp16 m16n8k16, BM=BN=128, BK=32 halves, double-buffered, ldmatrix.
// 8 warps, warp tile 64x32. Grid (64, 157).
// ---------------------------------------------------------------------------
__global__ __launch_bounds__(256, 2)
void laplace_gemm_kernel(const void* __restrict__ bwp) {
    __shared__ uint32_t Xs[2][128][PADW];   // 16 data words (32 halves) + 4 pad
    __shared__ uint32_t Zs[2][128][PADW];

    const int bm = blockIdx.x;      // 0..63
    const int bn = blockIdx.y;      // 0..156
    const int tid = threadIdx.x;
    const int lane = tid & 31;
    const int wid = tid >> 5;
    const int wm = (wid & 1) * 64;
    const int wn = (wid >> 1) * 32;

    float acc[4][4][4];
#pragma unroll
    for (int mt = 0; mt < 4; mt++)
#pragma unroll
        for (int nt = 0; nt < 4; nt++)
#pragma unroll
            for (int i = 0; i < 4; i++) acc[mt][nt][i] = 0.f;

    // Staging: thread covers 32B (16 halves) of one 128-row tile for X and Z.
    const int lr = tid >> 1;               // 0..127
    const int hs = (tid & 1);              // half selector
    const int wo = hs * 8;                 // word offset in smem row
    const __half* xg = g_Xh + (size_t)(bm * 128 + lr) * DD + hs * 16;
    const __half* zg = g_Zh + (size_t)(bn * 128 + lr) * DD + hs * 16;

    // ldmatrix lane addressing constants
    const int a_row = lane & 15;
    const int a_byte = (lane >> 4) * 16;
    const int b_row = (lane & 7) + ((lane & 16) >> 1);
    const int b_byte = (lane & 8) << 1;
    const uint32_t xsb = smem_u32(&Xs[0][0][0]);
    const uint32_t zsb = smem_u32(&Zs[0][0][0]);
    const uint32_t BUFB = 128 * PADW * 4;   // 10240

    // Prologue: tile 0
    uint4 xa0 = *(const uint4*)(xg);
    uint4 xa1 = *(const uint4*)(xg + 8);
    uint4 za0 = *(const uint4*)(zg);
    uint4 za1 = *(const uint4*)(zg + 8);
    *(uint4*)&Xs[0][lr][wo] = xa0;  *(uint4*)&Xs[0][lr][wo + 4] = xa1;
    *(uint4*)&Zs[0][lr][wo] = za0;  *(uint4*)&Zs[0][lr][wo + 4] = za1;
    __syncthreads();

    const int KT = DD / 32;   // 32
    for (int kt = 0; kt < KT; kt++) {
        const int buf = kt & 1;
        if (kt + 1 < KT) {
            const size_t off = (size_t)(kt + 1) * 32;
            xa0 = *(const uint4*)(xg + off);
            xa1 = *(const uint4*)(xg + off + 8);
            za0 = *(const uint4*)(zg + off);
            za1 = *(const uint4*)(zg + off + 8);
        }

#pragma unroll
        for (int kk = 0; kk < 2; kk++) {
            uint32_t a[4][4], b[4][2];
#pragma unroll
            for (int mt = 0; mt < 4; mt++) {
                uint32_t addr = xsb + buf * BUFB + (wm + mt * 16 + a_row) * (PADW * 4)
                              + a_byte + kk * 32;
                ldsm_x4(a[mt], addr);
            }
#pragma unroll
            for (int nt2 = 0; nt2 < 2; nt2++) {
                uint32_t r4[4];
                uint32_t addr = zsb + buf * BUFB + (wn + nt2 * 16 + b_row) * (PADW * 4)
                              + b_byte + kk * 32;
                ldsm_x4(r4, addr);
                b[nt2 * 2][0] = r4[0];  b[nt2 * 2][1] = r4[1];
                b[nt2 * 2 + 1][0] = r4[2];  b[nt2 * 2 + 1][1] = r4[3];
            }
#pragma unroll
            for (int mt = 0; mt < 4; mt++)
#pragma unroll
                for (int nt = 0; nt < 4; nt++)
                    mma_f16(acc[mt][nt], a[mt], b[nt]);
        }

        if (kt + 1 < KT) {
            const int nb = buf ^ 1;
            *(uint4*)&Xs[nb][lr][wo] = xa0;  *(uint4*)&Xs[nb][lr][wo + 4] = xa1;
            *(uint4*)&Zs[nb][lr][wo] = za0;  *(uint4*)&Zs[nb][lr][wo + 4] = za1;
        }
        __syncthreads();
    }

    // Epilogue: d2 -> exp(-d/bw) -> g_K (fp16)
    const float inv_bw = 1.0f / resolve_bw(bwp);
#pragma unroll
    for (int mt = 0; mt < 4; mt++) {
        const int r0 = bm * 128 + wm + mt * 16 + (lane >> 2);
        const float xs0 = g_xsq[r0];
        const float xs1 = g_xsq[r0 + 8];
#pragma unroll
        for (int nt = 0; nt < 4; nt++) {
            const int c0 = bn * 128 + wn + nt * 8 + ((lane & 3) << 1);
            const float zs0 = g_zsq[c0];
            const float zs1 = g_zsq[c0 + 1];
            float f0 = __expf(-sqrtf(fmaxf(xs0 + zs0 - 2.f * acc[mt][nt][0], 0.f)) * inv_bw);
            float f1 = __expf(-sqrtf(fmaxf(xs0 + zs1 - 2.f * acc[mt][nt][1], 0.f)) * inv_bw);
            *(__half2*)&g_K[(size_t)r0 * MP + c0] = __floats2half2_rn(f0, f1);
            f0 = __expf(-sqrtf(fmaxf(xs1 + zs0 - 2.f * acc[mt][nt][2], 0.f)) * inv_bw);
            f1 = __expf(-sqrtf(fmaxf(xs1 + zs1 - 2.f * acc[mt][nt][3], 0.f)) * inv_bw);
            *(__half2*)&g_K[(size_t)(r0 + 8) * MP + c0] = __floats2half2_rn(f0, f1);
        }
    }
}

// ---------------------------------------------------------------------------
// Kernel 2: pred = K @ W  (NT: A=g_K fp16 [NQ,MP], B=g_Wt fp16 [YY,MP]).
// BM=64, BN=128, BK=32, grid (128, 2). Warp tile 32x32, ldmatrix frags.
// ---------------------------------------------------------------------------
__global__ __launch_bounds__(256, 2)
void wgemm_kernel(float* __restrict__ out) {
    __shared__ uint32_t As[2][64][PADW];
    __shared__ uint32_t Bs[2][128][PADW];

    const int bm = blockIdx.x;   // 0..127
    const int bn = blockIdx.y;   // 0..1
    const int tid = threadIdx.x;
    const int lane = tid & 31;
    const int wid = tid >> 5;
    const int wm = (wid & 1) * 32;
    const int wn = (wid >> 1) * 32;

    float acc[2][4][4];
#pragma unroll
    for (int mt = 0; mt < 2; mt++)
#pragma unroll
        for (int nt = 0; nt < 4; nt++)
#pragma unroll
            for (int i = 0; i < 4; i++) acc[mt][nt][i] = 0.f;

    const int alr = tid >> 2;
    const int awo = (tid & 3) * 4;
    const size_t abase = (size_t)(bm * 64 + alr) * MP + awo * 2;
    const int blr = tid >> 1;
    const int bwo = (tid & 1) * 8;
    const size_t bbase = (size_t)blr * MP + bwo * 2;
    const size_t bcol = (size_t)bn * 128 * MP;

    const int a_row = lane & 15;
    const int a_byte = (lane >> 4) * 16;
    const int b_row = (lane & 7) + ((lane & 16) >> 1);
    const int b_byte = (lane & 8) << 1;
    const uint32_t asb = smem_u32(&As[0][0][0]);
    const uint32_t bsb = smem_u32(&Bs[0][0][0]);
    const uint32_t ABUF = 64 * PADW * 4;    // 5120
    const uint32_t BBUF = 128 * PADW * 4;   // 10240

    {
        uint4 ua = *(const uint4*)(g_K + abase);
        uint4 ub0 = *(const uint4*)(g_Wt + bcol + bbase);
        uint4 ub1 = *(const uint4*)(g_Wt + bcol + bbase + 8);
        *(uint4*)&As[0][alr][awo] = ua;
        *(uint4*)&Bs[0][blr][bwo] = ub0;
        *(uint4*)&Bs[0][blr][bwo + 4] = ub1;
    }
    __syncthreads();

    const int KT = MP / 32;   // 628
    for (int kt = 0; kt < KT; kt++) {
        const int buf = kt & 1;
        uint4 ua, ub0, ub1;
        if (kt + 1 < KT) {
            const size_t off = (size_t)(kt + 1) * 32;
            ua  = *(const uint4*)(g_K + abase + off);
            ub0 = *(const uint4*)(g_Wt + bcol + bbase + off);
            ub1 = *(const uint4*)(g_Wt + bcol + bbase + off + 8);
        }

#pragma unroll
        for (int kk = 0; kk < 2; kk++) {
            uint32_t a[2][4], b[4][2];
#pragma unroll
            for (int mt = 0; mt < 2; mt++) {
                uint32_t addr = asb + buf * ABUF + (wm + mt * 16 + a_row) * (PADW * 4)
                              + a_byte + kk * 32;
                ldsm_x4(a[mt], addr);
            }
#pragma unroll
            for (int nt2 = 0; nt2 < 2; nt2++) {
                uint32_t r4[4];
                uint32_t addr = bsb + buf * BBUF + (wn + nt2 * 16 + b_row) * (PADW * 4)
                              + b_byte + kk * 32;
                ldsm_x4(r4, addr);
                b[nt2 * 2][0] = r4[0];  b[nt2 * 2][1] = r4[1];
                b[nt2 * 2 + 1][0] = r4[2];  b[nt2 * 2 + 1][1] = r4[3];
            }
#pragma unroll
            for (int mt = 0; mt < 2; mt++)
#pragma unroll
                for (int nt = 0; nt < 4; nt++)
                    mma_f16(acc[mt][nt], a[mt], b[nt]);
        }

        if (kt + 1 < KT) {
            const int nb = buf ^ 1;
            *(uint4*)&As[nb][alr][awo] = ua;
            *(uint4*)&Bs[nb][blr][bwo] = ub0;
            *(uint4*)&Bs[nb][blr][bwo + 4] = ub1;
        }
        __syncthreads();
    }

#pragma unroll
    for (int mt = 0; mt < 2; mt++) {
        const int r0 = bm * 64 + wm + mt * 16 + (lane >> 2);
#pragma unroll
        for (int nt = 0; nt < 4; nt++) {
            const int c0 = bn * 128 + wn + nt * 8 + ((lane & 3) << 1);
            *(float2*)(out + (size_t)r0 * YY + c0) =
                make_float2(acc[mt][nt][0], acc[mt][nt][1]);
            *(float2*)(out + (size_t)(r0 + 8) * YY + c0) =
                make_float2(acc[mt][nt][2], acc[mt][nt][3]);
        }
    }
}

// ---------------------------------------------------------------------------
// Entry point (graph-capturable: launches only)
// ---------------------------------------------------------------------------
extern "C" void kernel_launch(void* const* d_in, const int* in_sizes, int n_in,
                              void* d_out, int out_size) {
    const float* batch   = (const float*)d_in[0];
    const float* centers = (const float*)d_in[1];
    const float* weight  = (const float*)d_in[2];
    const void*  bwp     = d_in[3];

    {
        int warps = NQ + MC;
        int blocks = (warps * 32 + 255) / 256;
        convert_kernel<<<blocks, 256>>>(batch, centers);
    }
    {
        dim3 grid(MC / 32, YY / 32);            // (625, 8)
        wtrans_kernel<<<grid, dim3(32, 32)>>>(weight);
    }
    {
        dim3 grid(NQ / 128, (MC + 127) / 128);  // (64, 157)
        laplace_gemm_kernel<<<grid, 256>>>(bwp);
    }
    {
        dim3 grid(NQ / 64, YY / 128);           // (128, 2)
        wgemm_kernel<<<grid, 256>>>((float*)d_out);
    }
}

// round 12
// speedup vs baseline: 1.1716x; 1.1716x over previous
#include <cuda_runtime.h>
#include <cuda_fp16.h>
#include <cstdint>
#include <cstddef>

// Problem dims
#define NQ 8192
#define MC 20000
#define MP 20096            // centers padded: 157*128
#define DD 1024
#define YY 256
#define PADW 20             // smem row stride in 32-bit words (conflict-free walk)

// Scratch (device globals; zero-initialized at load)
__device__ __half g_K[(size_t)NQ * MP];    // fp16 kernel matrix
__device__ __half g_Wt[(size_t)YY * MP];   // W transposed, k-contiguous; tail 0
__device__ __half g_Xh[(size_t)NQ * DD];   // fp16 batch
__device__ __half g_Zh[(size_t)MP * DD];   // fp16 centers; tail rows stay 0
__device__ float  g_xsq[NQ];
__device__ float  g_zsq[MP];               // tail stays 0

// ---------------------------------------------------------------------------
// Helpers
// ---------------------------------------------------------------------------
// fp16 inputs, fp32 accumulators (wgemm)
__device__ __forceinline__ void mma_f16_f32(float* c, const uint32_t* a, const uint32_t* b) {
    asm volatile(
        "mma.sync.aligned.m16n8k16.row.col.f32.f16.f16.f32 "
        "{%0,%1,%2,%3},{%4,%5,%6,%7},{%8,%9},{%0,%1,%2,%3};"
        : "+f"(c[0]), "+f"(c[1]), "+f"(c[2]), "+f"(c[3])
        : "r"(a[0]), "r"(a[1]), "r"(a[2]), "r"(a[3]), "r"(b[0]), "r"(b[1]));
}

// fp16 inputs, fp16 accumulators (GEMM1 — tests the 2x f16-acc rate)
__device__ __forceinline__ void mma_f16_f16(uint32_t* c, const uint32_t* a, const uint32_t* b) {
    asm volatile(
        "mma.sync.aligned.m16n8k16.row.col.f16.f16.f16.f16 "
        "{%0,%1},{%2,%3,%4,%5},{%6,%7},{%0,%1};"
        : "+r"(c[0]), "+r"(c[1])
        : "r"(a[0]), "r"(a[1]), "r"(a[2]), "r"(a[3]), "r"(b[0]), "r"(b[1]));
}

__device__ __forceinline__ uint32_t h2u(__half2 h) {
    return *reinterpret_cast<uint32_t*>(&h);
}

__device__ __forceinline__ float resolve_bw(const void* p) {
    int iv = *(const int*)p;
    if (iv > 0 && iv < 1000000) return (float)iv;
    return *(const float*)p;
}

// ---------------------------------------------------------------------------
// Kernel 0: convert fp32 rows -> fp16 AND compute exact fp32 row sq-norms.
// ---------------------------------------------------------------------------
__global__ void convert_kernel(const float* __restrict__ x, const float* __restrict__ z) {
    int gwarp = (blockIdx.x * blockDim.x + threadIdx.x) >> 5;
    int lane = threadIdx.x & 31;
    const float* src;
    __half* dh;
    float* dsq;
    if (gwarp < NQ) {
        src = x + (size_t)gwarp * DD; dh = g_Xh + (size_t)gwarp * DD; dsq = g_xsq + gwarp;
    } else if (gwarp < NQ + MC) {
        int r = gwarp - NQ;
        src = z + (size_t)r * DD;     dh = g_Zh + (size_t)r * DD;     dsq = g_zsq + r;
    } else return;

    const float4* p = (const float4*)src;
    uint2* o = (uint2*)dh;
    float s = 0.f;
#pragma unroll
    for (int i = 0; i < DD / 128; i++) {
        float4 v = p[lane + i * 32];
        s += v.x * v.x + v.y * v.y + v.z * v.z + v.w * v.w;
        o[lane + i * 32] = make_uint2(h2u(__floats2half2_rn(v.x, v.y)),
                                      h2u(__floats2half2_rn(v.z, v.w)));
    }
#pragma unroll
    for (int off = 16; off; off >>= 1) s += __shfl_xor_sync(0xffffffffu, s, off);
    if (lane == 0) *dsq = s;
}

// ---------------------------------------------------------------------------
// Kernel 0b: transpose W [MC, YY] fp32 -> g_Wt [YY, MP] fp16
// ---------------------------------------------------------------------------
__global__ void wtrans_kernel(const float* __restrict__ W) {
    __shared__ float t[32][33];
    const int k0 = blockIdx.x * 32;
    const int n0 = blockIdx.y * 32;
    const int tx = threadIdx.x, ty = threadIdx.y;
    t[ty][tx] = W[(size_t)(k0 + ty) * YY + (n0 + tx)];
    __syncthreads();
    g_Wt[(size_t)(n0 + ty) * MP + (k0 + tx)] = __float2half_rn(t[tx][ty]);
}

// ---------------------------------------------------------------------------
// Kernel 1: K[i,j] = exp(-sqrt(max(xsq+zsq-2*X.Z,0))/bw), fp16 out.
// NT GEMM fp16 m16n8k16 with F16 ACCUMULATORS, BM=BN=128, BK=32,
// double-buffered, scalar LDS frags. 8 warps, warp tile 64x32. Grid (64,157).
// ---------------------------------------------------------------------------
__global__ __launch_bounds__(256, 2)
void laplace_gemm_kernel(const void* __restrict__ bwp) {
    __shared__ uint32_t Xs[2][128][PADW];   // 16 data words (32 halves) + 4 pad
    __shared__ uint32_t Zs[2][128][PADW];

    const int bm = blockIdx.x;      // 0..63
    const int bn = blockIdx.y;      // 0..156
    const int tid = threadIdx.x;
    const int lane = tid & 31;
    const int wid = tid >> 5;
    const int wm = (wid & 1) * 64;
    const int wn = (wid >> 1) * 32;

    uint32_t acc[4][4][2];          // f16x2 accumulators
#pragma unroll
    for (int mt = 0; mt < 4; mt++)
#pragma unroll
        for (int nt = 0; nt < 4; nt++) { acc[mt][nt][0] = 0u; acc[mt][nt][1] = 0u; }

    // Staging: thread copies 32B (16 halves) per tile for X and Z (pure copy).
    const int lr = tid >> 1;
    const int hs = (tid & 1);
    const int wo = hs * 8;
    const __half* xg = g_Xh + (size_t)(bm * 128 + lr) * DD + hs * 16;
    const __half* zg = g_Zh + (size_t)(bn * 128 + lr) * DD + hs * 16;

    // Prologue: tile 0
    uint4 xa0 = *(const uint4*)(xg);
    uint4 xa1 = *(const uint4*)(xg + 8);
    uint4 za0 = *(const uint4*)(zg);
    uint4 za1 = *(const uint4*)(zg + 8);
    *(uint4*)&Xs[0][lr][wo] = xa0;  *(uint4*)&Xs[0][lr][wo + 4] = xa1;
    *(uint4*)&Zs[0][lr][wo] = za0;  *(uint4*)&Zs[0][lr][wo + 4] = za1;
    __syncthreads();

    const int KT = DD / 32;   // 32
    for (int kt = 0; kt < KT; kt++) {
        const int buf = kt & 1;
        if (kt + 1 < KT) {
            const size_t off = (size_t)(kt + 1) * 32;
            xa0 = *(const uint4*)(xg + off);
            xa1 = *(const uint4*)(xg + off + 8);
            za0 = *(const uint4*)(zg + off);
            za1 = *(const uint4*)(zg + off + 8);
        }

#pragma unroll
        for (int kk = 0; kk < 2; kk++) {
            const int kw = kk * 8 + (lane & 3);
            const int frow = lane >> 2;
            uint32_t a[4][4], b[4][2];
#pragma unroll
            for (int mt = 0; mt < 4; mt++) {
                int r = wm + mt * 16 + frow;
                a[mt][0] = Xs[buf][r][kw];
                a[mt][1] = Xs[buf][r + 8][kw];
                a[mt][2] = Xs[buf][r][kw + 4];
                a[mt][3] = Xs[buf][r + 8][kw + 4];
            }
#pragma unroll
            for (int nt = 0; nt < 4; nt++) {
                int c = wn + nt * 8 + frow;
                b[nt][0] = Zs[buf][c][kw];
                b[nt][1] = Zs[buf][c][kw + 4];
            }
#pragma unroll
            for (int mt = 0; mt < 4; mt++)
#pragma unroll
                for (int nt = 0; nt < 4; nt++)
                    mma_f16_f16(acc[mt][nt], a[mt], b[nt]);
        }

        if (kt + 1 < KT) {
            const int nb = buf ^ 1;
            *(uint4*)&Xs[nb][lr][wo] = xa0;  *(uint4*)&Xs[nb][lr][wo + 4] = xa1;
            *(uint4*)&Zs[nb][lr][wo] = za0;  *(uint4*)&Zs[nb][lr][wo + 4] = za1;
        }
        __syncthreads();
    }

    // Epilogue: unpack f16 dot, d2 -> exp(-d/bw) -> g_K (fp16)
    const float inv_bw = 1.0f / resolve_bw(bwp);
#pragma unroll
    for (int mt = 0; mt < 4; mt++) {
        const int r0 = bm * 128 + wm + mt * 16 + (lane >> 2);
        const float xs0 = g_xsq[r0];
        const float xs1 = g_xsq[r0 + 8];
#pragma unroll
        for (int nt = 0; nt < 4; nt++) {
            const int c0 = bn * 128 + wn + nt * 8 + ((lane & 3) << 1);
            const float zs0 = g_zsq[c0];
            const float zs1 = g_zsq[c0 + 1];
            float2 v0 = __half22float2(*(__half2*)&acc[mt][nt][0]);
            float2 v1 = __half22float2(*(__half2*)&acc[mt][nt][1]);
            float f0 = __expf(-sqrtf(fmaxf(xs0 + zs0 - 2.f * v0.x, 0.f)) * inv_bw);
            float f1 = __expf(-sqrtf(fmaxf(xs0 + zs1 - 2.f * v0.y, 0.f)) * inv_bw);
            *(__half2*)&g_K[(size_t)r0 * MP + c0] = __floats2half2_rn(f0, f1);
            f0 = __expf(-sqrtf(fmaxf(xs1 + zs0 - 2.f * v1.x, 0.f)) * inv_bw);
            f1 = __expf(-sqrtf(fmaxf(xs1 + zs1 - 2.f * v1.y, 0.f)) * inv_bw);
            *(__half2*)&g_K[(size_t)(r0 + 8) * MP + c0] = __floats2half2_rn(f0, f1);
        }
    }
}

// ---------------------------------------------------------------------------
// Kernel 2: pred = K @ W  (NT: A=g_K fp16 [NQ,MP], B=g_Wt fp16 [YY,MP]).
// BM=32, BN=128, BK=32, 128 threads (4 warps, warp tile 32x32 over n).
// Grid (256, 2) = 512 CTAs, ~4 CTAs/SM -> latency hiding. f32 accumulators.
// ---------------------------------------------------------------------------
__global__ __launch_bounds__(128, 4)
void wgemm_kernel(float* __restrict__ out) {
    __shared__ uint32_t As[2][32][PADW];
    __shared__ uint32_t Bs[2][128][PADW];

    const int bm = blockIdx.x;   // 0..255
    const int bn = blockIdx.y;   // 0..1
    const int tid = threadIdx.x;
    const int lane = tid & 31;
    const int wid = tid >> 5;    // 0..3
    const int wn = wid * 32;

    float acc[2][4][4];
#pragma unroll
    for (int mt = 0; mt < 2; mt++)
#pragma unroll
        for (int nt = 0; nt < 4; nt++)
#pragma unroll
            for (int i = 0; i < 4; i++) acc[mt][nt][i] = 0.f;

    // A staging: 32 rows x 16 words; thread: row tid>>2, 1 uint4 at (tid&3)*4
    const int alr = tid >> 2;
    const int awo = (tid & 3) * 4;
    const size_t abase = (size_t)(bm * 32 + alr) * MP + awo * 2;
    // B staging: 128 rows x 16 words; thread owns full row tid (4 uint4)
    const size_t bbase = (size_t)(bn * 128 + tid) * MP;

    // Prologue
    uint4 ua = *(const uint4*)(g_K + abase);
    uint4 ub[4];
#pragma unroll
    for (int j = 0; j < 4; j++) ub[j] = *(const uint4*)(g_Wt + bbase + j * 8);
    *(uint4*)&As[0][alr][awo] = ua;
#pragma unroll
    for (int j = 0; j < 4; j++) *(uint4*)&Bs[0][tid][j * 4] = ub[j];
    __syncthreads();

    const int KT = MP / 32;   // 628
    for (int kt = 0; kt < KT; kt++) {
        const int buf = kt & 1;
        if (kt + 1 < KT) {
            const size_t off = (size_t)(kt + 1) * 32;
            ua = *(const uint4*)(g_K + abase + off);
#pragma unroll
            for (int j = 0; j < 4; j++) ub[j] = *(const uint4*)(g_Wt + bbase + off + j * 8);
        }

#pragma unroll
        for (int kk = 0; kk < 2; kk++) {
            const int kw = kk * 8 + (lane & 3);
            const int frow = lane >> 2;
            uint32_t a[2][4], b[4][2];
#pragma unroll
            for (int mt = 0; mt < 2; mt++) {
                int r = mt * 16 + frow;
                a[mt][0] = As[buf][r][kw];
                a[mt][1] = As[buf][r + 8][kw];
                a[mt][2] = As[buf][r][kw + 4];
                a[mt][3] = As[buf][r + 8][kw + 4];
            }
#pragma unroll
            for (int nt = 0; nt < 4; nt++) {
                int c = wn + nt * 8 + frow;
                b[nt][0] = Bs[buf][c][kw];
                b[nt][1] = Bs[buf][c][kw + 4];
            }
#pragma unroll
            for (int mt = 0; mt < 2; mt++)
#pragma unroll
                for (int nt = 0; nt < 4; nt++)
                    mma_f16_f32(acc[mt][nt], a[mt], b[nt]);
        }

        if (kt + 1 < KT) {
            const int nb = buf ^ 1;
            *(uint4*)&As[nb][alr][awo] = ua;
#pragma unroll
            for (int j = 0; j < 4; j++) *(uint4*)&Bs[nb][tid][j * 4] = ub[j];
        }
        __syncthreads();
    }

#pragma unroll
    for (int mt = 0; mt < 2; mt++) {
        const int r0 = bm * 32 + mt * 16 + (lane >> 2);
#pragma unroll
        for (int nt = 0; nt < 4; nt++) {
            const int c0 = bn * 128 + wn + nt * 8 + ((lane & 3) << 1);
            *(float2*)(out + (size_t)r0 * YY + c0) =
                make_float2(acc[mt][nt][0], acc[mt][nt][1]);
            *(float2*)(out + (size_t)(r0 + 8) * YY + c0) =
                make_float2(acc[mt][nt][2], acc[mt][nt][3]);
        }
    }
}

// ---------------------------------------------------------------------------
// Entry point (graph-capturable: launches only)
// ---------------------------------------------------------------------------
extern "C" void kernel_launch(void* const* d_in, const int* in_sizes, int n_in,
                              void* d_out, int out_size) {
    const float* batch   = (const float*)d_in[0];
    const float* centers = (const float*)d_in[1];
    const float* weight  = (const float*)d_in[2];
    const void*  bwp     = d_in[3];

    {
        int warps = NQ + MC;
        int blocks = (warps * 32 + 255) / 256;
        convert_kernel<<<blocks, 256>>>(batch, centers);
    }
    {
        dim3 grid(MC / 32, YY / 32);            // (625, 8)
        wtrans_kernel<<<grid, dim3(32, 32)>>>(weight);
    }
    {
        dim3 grid(NQ / 128, (MC + 127) / 128);  // (64, 157)
        laplace_gemm_kernel<<<grid, 256>>>(bwp);
    }
    {
        dim3 grid(NQ / 32, YY / 128);           // (256, 2)
        wgemm_kernel<<<grid, 128>>>((float*)d_out);
    }
}